// round 16
// baseline (speedup 1.0000x reference)
#include <cuda_runtime.h>
#include <cuda_bf16.h>

#define BS   8
#define SEQ  2048
#define DIN  2048
#define DOUT 2048
#define SCALING 2.0f   // 16.0 / R (folded into B at staging)

typedef unsigned long long u64;

// ---- f32x2 packed-math helpers (sm_100+) -----------------------------------
__device__ __forceinline__ u64 ffma2(u64 a, u64 b, u64 c) {
    u64 d;
    asm("fma.rn.f32x2 %0, %1, %2, %3;" : "=l"(d) : "l"(a), "l"(b), "l"(c));
    return d;
}
__device__ __forceinline__ u64 addx2(u64 a, u64 b) {
    u64 d;
    asm("add.rn.f32x2 %0, %1, %2;" : "=l"(d) : "l"(a), "l"(b));
    return d;
}
__device__ __forceinline__ u64 rep2(float x) {
    u64 r; asm("mov.b64 %0, {%1, %1};" : "=l"(r) : "f"(x)); return r;
}
__device__ __forceinline__ u64 pk2(float lo, float hi) {
    u64 r; asm("mov.b64 %0, {%1, %2};" : "=l"(r) : "f"(lo), "f"(hi)); return r;
}
__device__ __forceinline__ void upk2(u64 v, float& lo, float& hi) {
    asm("mov.b64 {%0, %1}, %2;" : "=f"(lo), "=f"(hi) : "l"(v));
}

// ---------------------------------------------------------------------------
// Single fused kernel, warp-autonomous, NO barriers in the main work.
// Each warp owns ONE 8-row group -> smem A/B reads amortize over 2x the x/out
// bytes vs the 4-row version (LDS/SM traffic halved).
//
// smem (dynamic 128 KB):
//   At2[j][rp][d4] u64 = { A[rp][d4*4+j],  A[rp+4][d4*4+j] }        (64 KB)
//   Bs2[k][rp][o4] u64 = { S*B[rp][o4*4+k], S*B[rp+4][o4*4+k] }     (64 KB)
//
// Loop over c (d4 = c*32+lane):
//   p1: 8 LDG.128 (rows), 16 LDS.64 (A planes), rank-packed FFMA2 into 32 u64.
//   One full 32-value packed butterfly -> lane m = row*4+rp holds
//   {xa[row][rp], xa[row][rp+4]}.
//   p2: 16 LDS.64 (B planes) per c, FFMA2 with shfl'd packed multipliers,
//   fold halves, STG.128 streaming stores.
// Grid (18, 8): 288 warp-slots cover 256 groups/batch; 144 SMs pull HBM.
// ---------------------------------------------------------------------------
__global__ __launch_bounds__(512, 1) void k_main(
    const float* __restrict__ x, float* __restrict__ out,
    const float* __restrict__ ctr, const float* __restrict__ gamma,
    const float* __restrict__ beta, const float* __restrict__ W1,
    const float* __restrict__ b1, const float* __restrict__ W2,
    const float* __restrict__ b2, const float* __restrict__ Wa,
    const float* __restrict__ Wb)
{
    extern __shared__ u64 sdyn[];          // [0,8192) = At2, [8192,16384) = Bs2
    u64* At2 = sdyn;
    u64* Bs2 = sdyn + 8192;
    __shared__ float zs[32];
    __shared__ float hs[64];
    __shared__ float graw[4];

    const int b = blockIdx.y;
    const int tid = threadIdx.x;
    const int warp = tid >> 5, lane = tid & 31;

    // ---- gate MLP (one-time; barriers fine here) ----
    if (tid < 32) {
        float v = ctr[b * 32 + tid];
        float s = v;
        #pragma unroll
        for (int o = 16; o; o >>= 1) s += __shfl_xor_sync(0xffffffffu, s, o);
        float mu = s * (1.0f / 32.0f);
        float dv = v - mu;
        float s2 = dv * dv;
        #pragma unroll
        for (int o = 16; o; o >>= 1) s2 += __shfl_xor_sync(0xffffffffu, s2, o);
        zs[tid] = dv * rsqrtf(s2 * (1.0f / 32.0f) + 1e-5f) * gamma[tid] + beta[tid];
    }
    __syncthreads();
    if (tid < 64) {
        float h = 0.0f;
        if (tid < 60) {
            h = b1[tid];
            #pragma unroll
            for (int c = 0; c < 32; c++) h = fmaf(zs[c], W1[tid * 32 + c], h);
            h = fmaxf(h, 0.0f);
        }
        hs[tid] = h;
    }
    __syncthreads();
    if (tid < 4) {
        float s = b2[tid];
        #pragma unroll
        for (int j = 0; j < 60; j++) s = fmaf(hs[j], W2[tid * 60 + j], s);
        graw[tid] = s;
    }
    __syncthreads();
    if (tid < 4) {
        float m = fmaxf(fmaxf(graw[0], graw[1]), fmaxf(graw[2], graw[3]));
        float den = expf(graw[0] - m) + expf(graw[1] - m) +
                    expf(graw[2] - m) + expf(graw[3] - m);
        hs[tid] = expf(graw[tid] - m) / den;
    }
    __syncthreads();
    const float g0 = hs[0], g1 = hs[1], g2 = hs[2], g3 = hs[3];

    // ---- stage A into smem (coalesced float4 reads of Wa) ----
    #pragma unroll 4
    for (int i = 0; i < 16; i++) {
        int e = tid + i * 512;
        int rp = e >> 11, d = e & 2047;
        float4 wl = *(const float4*)(Wa + ((size_t)(rp * DIN + d) << 2));
        float4 wh = *(const float4*)(Wa + ((size_t)((rp + 4) * DIN + d) << 2));
        float alo = g0 * wl.x + g1 * wl.y + g2 * wl.z + g3 * wl.w;
        float ahi = g0 * wh.x + g1 * wh.y + g2 * wh.z + g3 * wh.w;
        At2[(((d & 3) * 4 + rp) << 9) + (d >> 2)] = pk2(alo, ahi);
    }
    // ---- stage B into smem (pre-scaled) ----
    #pragma unroll 4
    for (int i = 0; i < 16; i++) {
        int e = tid + i * 512;
        int rp = e >> 11, o = e & 2047;
        float4 wl = *(const float4*)(Wb + ((size_t)(rp * DOUT + o) << 2));
        float4 wh = *(const float4*)(Wb + ((size_t)((rp + 4) * DOUT + o) << 2));
        float blo = SCALING * (g0 * wl.x + g1 * wl.y + g2 * wl.z + g3 * wl.w);
        float bhi = SCALING * (g0 * wh.x + g1 * wh.y + g2 * wh.z + g3 * wh.w);
        Bs2[(((o & 3) * 4 + rp) << 9) + (o >> 2)] = pk2(blo, bhi);
    }
    __syncthreads();   // last barrier in the kernel

    const int gw = blockIdx.x * 16 + warp;   // 0..287; 256 real groups
    if (gw < 256) {
        const float* xb = x + (size_t)b * SEQ * DIN;
        float* ob = out + (size_t)b * SEQ * DOUT;
        const int s = gw * 8;

        // acc2[m], m = row*4 + rp, halves = (xa[row][rp], xa[row][rp+4])
        u64 acc2[32];
        #pragma unroll
        for (int v = 0; v < 32; v++) acc2[v] = 0ull;

        // ---- phase 1 ----
        #pragma unroll 1
        for (int c = 0; c < 16; c++) {
            const int d4 = c * 32 + lane;
            float4 xr[8];
            #pragma unroll
            for (int row = 0; row < 8; row++)
                xr[row] = __ldcs((const float4*)(xb + (size_t)(s + row) * DIN + (size_t)d4 * 4));
            #pragma unroll
            for (int j = 0; j < 4; j++) {
                u64 aj[4];
                #pragma unroll
                for (int rp = 0; rp < 4; rp++)
                    aj[rp] = At2[((j * 4 + rp) << 9) + d4];
                #pragma unroll
                for (int row = 0; row < 8; row++) {
                    u64 xj2 = rep2(((const float*)&xr[row])[j]);
                    #pragma unroll
                    for (int rp = 0; rp < 4; rp++)
                        acc2[row * 4 + rp] = ffma2(xj2, aj[rp], acc2[row * 4 + rp]);
                }
            }
        }

        // ---- full 32-value packed butterfly: lane l ends with value l ----
        #pragma unroll
        for (int off = 16; off >= 1; off >>= 1) {
            const bool up = (lane & off) != 0;
            #pragma unroll
            for (int i = 0; i < off; i++) {
                u64 send = up ? acc2[i] : acc2[off + i];
                u64 recv = __shfl_xor_sync(0xffffffffu, send, off);
                u64 keep = up ? acc2[off + i] : acc2[i];
                acc2[i] = addx2(keep, recv);
            }
        }
        // lane m = row*4+rp holds packed {xa[row][rp], xa[row][rp+4]} in acc2[0]
        const u64 my_xa = acc2[0];

        // broadcast all 32 packed multipliers
        u64 xm[32];
        #pragma unroll
        for (int m = 0; m < 32; m++)
            xm[m] = __shfl_sync(0xffffffffu, my_xa, m);

        // ---- phase 2 ----
        #pragma unroll 1
        for (int c = 0; c < 16; c++) {
            const int o4 = c * 32 + lane;
            u64 bk[16];
            #pragma unroll
            for (int k = 0; k < 4; k++)
                #pragma unroll
                for (int rp = 0; rp < 4; rp++)
                    bk[k * 4 + rp] = Bs2[((k * 4 + rp) << 9) + o4];
            #pragma unroll
            for (int row = 0; row < 8; row++) {
                u64 o2[4];
                #pragma unroll
                for (int k = 0; k < 4; k++) o2[k] = 0ull;
                #pragma unroll
                for (int rp = 0; rp < 4; rp++)
                    #pragma unroll
                    for (int k = 0; k < 4; k++)
                        o2[k] = ffma2(xm[row * 4 + rp], bk[k * 4 + rp], o2[k]);
                float o[4];
                #pragma unroll
                for (int k = 0; k < 4; k++) {
                    float lo, hi;
                    upk2(o2[k], lo, hi);
                    o[k] = lo + hi;
                }
                __stcs((float4*)(ob + (size_t)(s + row) * DOUT + (size_t)o4 * 4),
                       make_float4(o[0], o[1], o[2], o[3]));
            }
        }
    }
}

// ---------------------------------------------------------------------------
extern "C" void kernel_launch(void* const* d_in, const int* in_sizes, int n_in,
                              void* d_out, int out_size)
{
    const float* x     = (const float*)d_in[0];
    const float* ctr   = (const float*)d_in[1];
    const float* gamma = (const float*)d_in[2];
    const float* beta  = (const float*)d_in[3];
    const float* W1    = (const float*)d_in[4];
    const float* b1    = (const float*)d_in[5];
    const float* W2    = (const float*)d_in[6];
    const float* b2    = (const float*)d_in[7];
    const float* Wa    = (const float*)d_in[8];
    const float* Wb    = (const float*)d_in[9];
    float* out = (float*)d_out;

    const int smem_bytes = 128 * 1024;
    cudaFuncSetAttribute(k_main, cudaFuncAttributeMaxDynamicSharedMemorySize,
                         smem_bytes);
    k_main<<<dim3(18, 8), 512, smem_bytes>>>(x, out, ctr, gamma, beta,
                                             W1, b1, W2, b2, Wa, Wb);
}